// round 14
// baseline (speedup 1.0000x reference)
#include <cuda_runtime.h>
#include <cuda_fp16.h>
#include <cuda.h>

// DSSIM — fused separable-Gaussian SSIM + mean.
// Round 14: 5 blocks/SM via TH=56 tile (smem 42.9KB) + launch_bounds(256,5).
// TMA window back to aligned [x0-8, x0+40). Math identical to round 10.

#define IMH 512
#define IMW 512
#define TW 32
#define TH 56
#define SROWS 66            // TH + 10
#define STP 48              // staging pitch floats (192B, aligned window x0-8)
#define HP 33               // sH pitch in 8B units
#define GX 16
#define GY 10
#define NBLK (GX*GY*96)     // 15360
#define NRED1 60
#define C1F 1.0e-4f
#define C2F 9.0e-4f
#define TMA_BYTES (2 * SROWS * STP * 4)   // 25344

typedef unsigned long long u64;

static __device__ __forceinline__ u64 pk2(float lo, float hi) {
    u64 r; asm("mov.b64 %0, {%1,%2};" : "=l"(r) : "f"(lo), "f"(hi)); return r;
}
static __device__ __forceinline__ void up2(u64 v, float& lo, float& hi) {
    asm("mov.b64 {%0,%1}, %2;" : "=f"(lo), "=f"(hi) : "l"(v));
}
static __device__ __forceinline__ u64 fma2(u64 a, u64 b, u64 c) {
    u64 d; asm("fma.rn.f32x2 %0, %1, %2, %3;" : "=l"(d) : "l"(a), "l"(b), "l"(c)); return d;
}
static __device__ __forceinline__ u64 add2(u64 a, u64 b) {
    u64 d; asm("add.rn.f32x2 %0, %1, %2;" : "=l"(d) : "l"(a), "l"(b)); return d;
}
static __device__ __forceinline__ unsigned smem32(const void* p) {
    unsigned a; asm("{ .reg .u64 t; cvta.to.shared.u64 t, %1; cvt.u32.u64 %0, t; }" : "=r"(a) : "l"(p));
    return a;
}

struct __align__(8) H2x2 { __half2 a, b; };   // (mu1', mu2'), (S', xy')

__device__ float  g_part[NBLK];
__device__ double g_part2[NRED1];

#define ACCS(kk, va, vb) do {                                           \
    const float _s  = fmaf((va), (va), (vb) * (vb));                    \
    const float _xy = (va) * (vb);                                      \
    const u64 _A = pk2((va), (vb));                                     \
    const u64 _B = pk2(_s, _xy);                                        \
    _Pragma("unroll")                                                   \
    for (int j = 0; j < 8; ++j) {                                       \
        const int t = (kk) - j;                                         \
        if (t >= 0 && t <= 10) {                                        \
            const int wi = (t < 6) ? t : 10 - t;                        \
            aA[j] = fma2(ww[wi], _A, aA[j]);                            \
            aB[j] = fma2(ww[wi], _B, aB[j]);                            \
        }                                                               \
    }                                                                   \
} while (0)

__global__ __launch_bounds__(256, 5) void dssim_tma(
    const __grid_constant__ CUtensorMap tm1,
    const __grid_constant__ CUtensorMap tm2,
    const float* __restrict__ kern)
{
    __shared__ alignas(128) float sT1[SROWS * STP];   // 12672 B
    __shared__ alignas(128) float sT2[SROWS * STP];   // 12672 B
    __shared__ alignas(16)  H2x2  sH[SROWS * HP];     // 17424 B
    __shared__ alignas(8)   u64   mbar;
    __shared__ float sW[6];
    __shared__ float sWarp[8];

    const int tid = threadIdx.x;
    const int x0 = blockIdx.x * TW;
    const int y0 = blockIdx.y * TH;

    if (tid == 0) {
        const unsigned mb = smem32(&mbar);
        asm volatile("mbarrier.init.shared.b64 [%0], 1;" :: "r"(mb) : "memory");
        asm volatile("fence.proxy.async.shared::cta;" ::: "memory");
        asm volatile("mbarrier.arrive.expect_tx.shared.b64 _, [%0], %1;"
                     :: "r"(mb), "r"((unsigned)TMA_BYTES) : "memory");
        const int cx = x0 - 8, cy = y0 - 5, cz = blockIdx.z;  // 32B-aligned start
        asm volatile("cp.async.bulk.tensor.3d.shared::cta.global.tile.mbarrier::complete_tx::bytes "
                     "[%0], [%1, {%2, %3, %4}], [%5];"
                     :: "r"(smem32(sT1)), "l"(&tm1), "r"(cx), "r"(cy), "r"(cz), "r"(mb) : "memory");
        asm volatile("cp.async.bulk.tensor.3d.shared::cta.global.tile.mbarrier::complete_tx::bytes "
                     "[%0], [%1, {%2, %3, %4}], [%5];"
                     :: "r"(smem32(sT2)), "l"(&tm2), "r"(cx), "r"(cy), "r"(cz), "r"(mb) : "memory");
    }
    if (tid < 6) {
        float s = 0.f;
        #pragma unroll
        for (int j = 0; j < 11; ++j) s += kern[tid * 11 + j];
        sW[tid] = s;
    }
    __syncthreads();

    u64 ww[6];
    #pragma unroll
    for (int i = 0; i < 6; ++i) { float w = sW[i]; ww[i] = pk2(w, w); }
    const u64 NEGH = pk2(-0.5f, -0.5f);

    {   // wait for TMA (acquire)
        const unsigned mb = smem32(&mbar);
        unsigned done;
        asm volatile("{\n\t.reg .pred p;\n\t"
                     "mbarrier.try_wait.parity.acquire.cta.shared::cta.b64 p, [%1], 0;\n\t"
                     "selp.b32 %0, 1, 0, p;\n\t}"
                     : "=r"(done) : "r"(mb) : "memory");
        if (!done) {
            asm volatile("{\n\t.reg .pred P1;\n\tW0_%=:\n\t"
                         "mbarrier.try_wait.parity.acquire.cta.shared::cta.b64 P1, [%0], 0, 0x989680;\n\t"
                         "@P1 bra.uni W1_%=;\n\tbra.uni W0_%=;\n\tW1_%=:\n\t}" :: "r"(mb) : "memory");
        }
    }

    // ---- H-pass: 264 tasks (66 rows x 4 groups-of-8); 6 LDS.128 per image ----
    // Output col cx+j, tap t: local L = cx + 3 + (j+t); quad qi covers k=4qi-3..4qi.
    for (int g = tid; g < SROWS * 4; g += 256) {
        const int r  = g >> 2;
        const int cx = (g & 3) << 3;
        u64 aA[8], aB[8];
        #pragma unroll
        for (int j = 0; j < 8; ++j) { aA[j] = 0ull; aB[j] = 0ull; }

        const float4* r1 = (const float4*)&sT1[r * STP];
        const float4* r2 = (const float4*)&sT2[r * STP];
        const int qb = cx >> 2;
        #pragma unroll
        for (int qi = 0; qi < 6; ++qi) {
            const float4 A4 = r1[qb + qi];
            const float4 B4 = r2[qb + qi];
            u64 pa, pb; float a0,a1,b0,b1,a2,a3,b2,b3;
            pa = add2(pk2(A4.x, A4.y), NEGH); up2(pa, a0, a1);
            pb = add2(pk2(B4.x, B4.y), NEGH); up2(pb, b0, b1);
            { const int k = 4 * qi - 3;
              if (k >= 0 && k <= 17) ACCS(k, a0, b0);
              if (k + 1 >= 0 && k + 1 <= 17) ACCS(k + 1, a1, b1); }
            pa = add2(pk2(A4.z, A4.w), NEGH); up2(pa, a2, a3);
            pb = add2(pk2(B4.z, B4.w), NEGH); up2(pb, b2, b3);
            { const int k = 4 * qi - 1;
              if (k >= 0 && k <= 17) ACCS(k, a2, b2);
              if (k + 1 <= 17) ACCS(k + 1, a3, b3); }
        }

        #pragma unroll
        for (int j = 0; j < 8; ++j) {
            float m1, m2, s, xy;
            up2(aA[j], m1, m2);
            up2(aB[j], s, xy);
            H2x2 h;
            h.a = __floats2half2_rn(m1, m2);
            h.b = __floats2half2_rn(s, xy);
            sH[r * HP + cx + j] = h;
        }
    }
    __syncthreads();

    // ---- V-pass + SSIM: 8 warps x 7 rows = 56 rows; 17 taps ----
    __half2 wh[6];
    #pragma unroll
    for (int i = 0; i < 6; ++i) wh[i] = __float2half2_rn(sW[i]);
    const int x  = tid & 31;
    const int ys = (tid >> 5) * 7;
    __half2 vA[7], vB[7];
    const __half2 hz = __float2half2_rn(0.f);
    #pragma unroll
    for (int j = 0; j < 7; ++j) { vA[j] = hz; vB[j] = hz; }
    #pragma unroll
    for (int k = 0; k < 17; ++k) {
        const H2x2 h = sH[(ys + k) * HP + x];
        #pragma unroll
        for (int j = 0; j < 7; ++j) {
            const int t = k - j;
            if (t >= 0 && t <= 10) {
                const int wi = (t < 6) ? t : 10 - t;
                vA[j] = __hfma2(wh[wi], h.a, vA[j]);
                vB[j] = __hfma2(wh[wi], h.b, vB[j]);
            }
        }
    }
    float local = 0.f;
    #pragma unroll
    for (int j = 0; j < 7; ++j) {
        if (y0 + ys + j < IMH) {                    // tail tile guard (560 > 512)
            const float2 m  = __half22float2(vA[j]);
            const float2 sx = __half22float2(vB[j]);
            const float t2 = m.x + m.y;
            const float p  = m.x * m.y;
            const float q2 = fmaf(m.x, m.x, m.y * m.y);
            const float mu12 = fmaf(0.5f, t2, p + 0.25f);
            const float A2   = q2 + t2 + 0.5f;
            const float num = fmaf(2.f, mu12, C1F) * fmaf(2.f, sx.y - p, C2F);
            const float den = (A2 + C1F) * ((sx.x - q2) + C2F);
            local += (1.f - __fdividef(num, den)) * 0.5f;
        }
    }
    #pragma unroll
    for (int o = 16; o; o >>= 1) local += __shfl_xor_sync(0xffffffffu, local, o);
    if ((tid & 31) == 0) sWarp[tid >> 5] = local;
    __syncthreads();
    if (tid == 0) {
        float bs = 0.f;
        #pragma unroll
        for (int i = 0; i < 8; ++i) bs += sWarp[i];
        g_part[((int)blockIdx.z * GY + (int)blockIdx.y) * GX + (int)blockIdx.x] = bs;
    }
}

// Naive fallback (only if tensormap encode fails); same grid/partial layout.
__global__ __launch_bounds__(256) void dssim_naive(
    const float* __restrict__ im1, const float* __restrict__ im2, const float* __restrict__ kern)
{
    __shared__ float sK[121], sWarp[8];
    const int tid = threadIdx.x;
    if (tid < 121) sK[tid] = kern[tid];
    __syncthreads();
    const int x = blockIdx.x * TW + (tid & 31);
    const int yb = blockIdx.y * TH + (tid >> 5) * 7;
    const size_t pb = (size_t)blockIdx.z * IMH * IMW;
    float local = 0.f;
    for (int py = 0; py < 7; ++py) {
        const int y = yb + py;
        if (y >= IMH) break;
        float m1 = 0, m2 = 0, xx = 0, yy = 0, xy = 0;
        for (int t = 0; t < 121; ++t) {
            const int gy = y + t / 11 - 5, gx = x + t % 11 - 5;
            float a = 0, b = 0;
            if ((unsigned)gy < IMH && (unsigned)gx < IMW) {
                a = im1[pb + (size_t)gy * IMW + gx]; b = im2[pb + (size_t)gy * IMW + gx];
            }
            const float w = sK[t];
            m1 += w * a; m2 += w * b; xx += w * a * a; yy += w * b * b; xy += w * a * b;
        }
        const float mu12 = m1 * m2, A2 = m1 * m1 + m2 * m2;
        const float num = (2.f * mu12 + C1F) * (2.f * (xy - mu12) + C2F);
        const float den = (A2 + C1F) * ((xx + yy - A2) + C2F);
        local += (1.f - num / den) * 0.5f;
    }
    #pragma unroll
    for (int o = 16; o; o >>= 1) local += __shfl_xor_sync(0xffffffffu, local, o);
    if ((tid & 31) == 0) sWarp[tid >> 5] = local;
    __syncthreads();
    if (tid == 0) {
        float bs = 0.f;
        #pragma unroll
        for (int i = 0; i < 8; ++i) bs += sWarp[i];
        g_part[((int)blockIdx.z * GY + (int)blockIdx.y) * GX + (int)blockIdx.x] = bs;
    }
}

__global__ __launch_bounds__(256) void dssim_reduce1()
{
    __shared__ double sd[256];
    const int t = threadIdx.x;
    sd[t] = (double)g_part[blockIdx.x * 256 + t];
    __syncthreads();
    #pragma unroll
    for (int o = 128; o; o >>= 1) { if (t < o) sd[t] += sd[t + o]; __syncthreads(); }
    if (t == 0) g_part2[blockIdx.x] = sd[0];
}

__global__ __launch_bounds__(64) void dssim_reduce2(float* __restrict__ out)
{
    __shared__ double sd[64];
    const int t = threadIdx.x;
    sd[t] = (t < NRED1) ? g_part2[t] : 0.0;
    __syncthreads();
    #pragma unroll
    for (int o = 32; o; o >>= 1) { if (t < o) sd[t] += sd[t + o]; __syncthreads(); }
    if (t == 0) out[0] = (float)(sd[0] / (double)(32.0 * 3.0 * 512.0 * 512.0));
}

typedef CUresult (*PFN_enc)(CUtensorMap*, CUtensorMapDataType, cuuint32_t, void*,
    const cuuint64_t*, const cuuint64_t*, const cuuint32_t*, const cuuint32_t*,
    CUtensorMapInterleave, CUtensorMapSwizzle, CUtensorMapL2promotion, CUtensorMapFloatOOBfill);

static bool build_tmap(PFN_enc enc, CUtensorMap* tm, const void* ptr)
{
    cuuint64_t dims[3] = {IMW, IMH, 96};
    cuuint64_t str[2] = {IMW * 4ull, (cuuint64_t)IMH * IMW * 4ull};
    cuuint32_t box[3] = {STP, SROWS, 1};
    cuuint32_t es[3] = {1, 1, 1};
    return enc(tm, CU_TENSOR_MAP_DATA_TYPE_FLOAT32, 3, (void*)ptr, dims, str, box, es,
               CU_TENSOR_MAP_INTERLEAVE_NONE, CU_TENSOR_MAP_SWIZZLE_NONE,
               CU_TENSOR_MAP_L2_PROMOTION_L2_128B, CU_TENSOR_MAP_FLOAT_OOB_FILL_NONE) == CUDA_SUCCESS;
}

extern "C" void kernel_launch(void* const* d_in, const int* in_sizes, int n_in,
                              void* d_out, int out_size)
{
    const float* im1 = (const float*)d_in[0];
    const float* im2 = (const float*)d_in[1];
    const float* kern = (const float*)d_in[2];
    float* out = (float*)d_out;
    dim3 grid(GX, GY, 96);   // 16 x 10 x 96 tiles of 32x56

    PFN_enc enc = nullptr;
    {
        void* fp = nullptr;
        cudaDriverEntryPointQueryResult st = cudaDriverEntryPointSymbolNotFound;
        if (cudaGetDriverEntryPoint("cuTensorMapEncodeTiled", &fp, cudaEnableDefault, &st) == cudaSuccess &&
            st == cudaDriverEntryPointSuccess)
            enc = (PFN_enc)fp;
    }
    CUtensorMap tm1, tm2;
    if (enc && build_tmap(enc, &tm1, im1) && build_tmap(enc, &tm2, im2))
        dssim_tma<<<grid, 256>>>(tm1, tm2, kern);
    else
        dssim_naive<<<grid, 256>>>(im1, im2, kern);

    dssim_reduce1<<<NRED1, 256>>>();
    dssim_reduce2<<<1, 64>>>(out);
}

// round 15
// speedup vs baseline: 1.0432x; 1.0432x over previous
#include <cuda_runtime.h>
#include <cuda_fp16.h>
#include <cuda.h>

// DSSIM — fused separable-Gaussian SSIM + mean.
// Round 15: round-10 geometry (TH=64, zero overhead) at 5 blocks/SM via
// chunked TMA staging (37-row reused buffer, smem 34KB). Math identical
// to round 10 (rel_err 1.389e-6).

#define IMH 512
#define IMW 512
#define TW 32
#define TH 64
#define SROWS 74            // TH + 10
#define CROWS 37            // rows per staging chunk
#define STP 48              // staging pitch floats (192B, window x0-8)
#define HP 33               // sH pitch in 8B units
#define GX 16
#define GY 8
#define NBLK (GX*GY*96)     // 12288
#define NRED1 48
#define C1F 1.0e-4f
#define C2F 9.0e-4f
#define CHUNK_BYTES (2 * CROWS * STP * 4)   // 14208

typedef unsigned long long u64;

static __device__ __forceinline__ u64 pk2(float lo, float hi) {
    u64 r; asm("mov.b64 %0, {%1,%2};" : "=l"(r) : "f"(lo), "f"(hi)); return r;
}
static __device__ __forceinline__ void up2(u64 v, float& lo, float& hi) {
    asm("mov.b64 {%0,%1}, %2;" : "=f"(lo), "=f"(hi) : "l"(v));
}
static __device__ __forceinline__ u64 fma2(u64 a, u64 b, u64 c) {
    u64 d; asm("fma.rn.f32x2 %0, %1, %2, %3;" : "=l"(d) : "l"(a), "l"(b), "l"(c)); return d;
}
static __device__ __forceinline__ u64 add2(u64 a, u64 b) {
    u64 d; asm("add.rn.f32x2 %0, %1, %2;" : "=l"(d) : "l"(a), "l"(b)); return d;
}
static __device__ __forceinline__ unsigned smem32(const void* p) {
    unsigned a; asm("{ .reg .u64 t; cvta.to.shared.u64 t, %1; cvt.u32.u64 %0, t; }" : "=r"(a) : "l"(p));
    return a;
}
static __device__ __forceinline__ void mwait(unsigned mb, unsigned phase) {
    unsigned done;
    asm volatile("{\n\t.reg .pred p;\n\t"
                 "mbarrier.try_wait.parity.acquire.cta.shared::cta.b64 p, [%1], %2;\n\t"
                 "selp.b32 %0, 1, 0, p;\n\t}"
                 : "=r"(done) : "r"(mb), "r"(phase) : "memory");
    if (!done) {
        asm volatile("{\n\t.reg .pred P1;\n\tW0_%=:\n\t"
                     "mbarrier.try_wait.parity.acquire.cta.shared::cta.b64 P1, [%0], %1, 0x989680;\n\t"
                     "@P1 bra.uni W1_%=;\n\tbra.uni W0_%=;\n\tW1_%=:\n\t}"
                     :: "r"(mb), "r"(phase) : "memory");
    }
}

struct __align__(8) H2x2 { __half2 a, b; };   // (mu1', mu2'), (S', xy')

__device__ float  g_part[NBLK];
__device__ double g_part2[NRED1];

#define ACCS(kk, va, vb) do {                                           \
    const float _s  = fmaf((va), (va), (vb) * (vb));                    \
    const float _xy = (va) * (vb);                                      \
    const u64 _A = pk2((va), (vb));                                     \
    const u64 _B = pk2(_s, _xy);                                        \
    _Pragma("unroll")                                                   \
    for (int j = 0; j < 8; ++j) {                                       \
        const int t = (kk) - j;                                         \
        if (t >= 0 && t <= 10) {                                        \
            const int wi = (t < 6) ? t : 10 - t;                        \
            aA[j] = fma2(ww[wi], _A, aA[j]);                            \
            aB[j] = fma2(ww[wi], _B, aB[j]);                            \
        }                                                               \
    }                                                                   \
} while (0)

#define TMA_CHUNK(cyv)                                                          \
    asm volatile("mbarrier.arrive.expect_tx.shared.b64 _, [%0], %1;"            \
                 :: "r"(mb), "r"((unsigned)CHUNK_BYTES) : "memory");            \
    asm volatile("cp.async.bulk.tensor.3d.shared::cta.global.tile.mbarrier::complete_tx::bytes " \
                 "[%0], [%1, {%2, %3, %4}], [%5];"                              \
                 :: "r"(smem32(sT1)), "l"(&tm1), "r"(x0 - 8), "r"(cyv), "r"((int)blockIdx.z), "r"(mb) : "memory"); \
    asm volatile("cp.async.bulk.tensor.3d.shared::cta.global.tile.mbarrier::complete_tx::bytes " \
                 "[%0], [%1, {%2, %3, %4}], [%5];"                              \
                 :: "r"(smem32(sT2)), "l"(&tm2), "r"(x0 - 8), "r"(cyv), "r"((int)blockIdx.z), "r"(mb) : "memory")

__global__ __launch_bounds__(256, 5) void dssim_tma(
    const __grid_constant__ CUtensorMap tm1,
    const __grid_constant__ CUtensorMap tm2,
    const float* __restrict__ kern)
{
    __shared__ alignas(128) float sT1[CROWS * STP];   // 7104 B (reused per chunk)
    __shared__ alignas(128) float sT2[CROWS * STP];   // 7104 B
    __shared__ alignas(16)  H2x2  sH[SROWS * HP];     // 19536 B
    __shared__ alignas(8)   u64   mbar;
    __shared__ float sW[6];
    __shared__ float sWarp[8];

    const int tid = threadIdx.x;
    const int x0 = blockIdx.x * TW;
    const int y0 = blockIdx.y * TH;
    const unsigned mb = smem32(&mbar);

    if (tid == 0) {
        asm volatile("mbarrier.init.shared.b64 [%0], 1;" :: "r"(mb) : "memory");
        asm volatile("fence.proxy.async.shared::cta;" ::: "memory");
        TMA_CHUNK(y0 - 5);                       // chunk 0: staged rows 0..36
    }
    if (tid < 6) {
        float s = 0.f;
        #pragma unroll
        for (int j = 0; j < 11; ++j) s += kern[tid * 11 + j];
        sW[tid] = s;
    }
    __syncthreads();   // orders mbarrier.init before other threads' waits

    u64 ww[6];
    #pragma unroll
    for (int i = 0; i < 6; ++i) { float w = sW[i]; ww[i] = pk2(w, w); }
    const u64 NEGH = pk2(-0.5f, -0.5f);

    // ---- H-pass in two chunks of 37 rows; buffer reused ----
    #pragma unroll 1
    for (int ch = 0; ch < 2; ++ch) {
        mwait(mb, (unsigned)ch);

        if (tid < CROWS * 4) {                   // 148 tasks
            const int rl = tid >> 2;             // row within chunk
            const int r  = ch * CROWS + rl;      // global staged row
            const int cx = (tid & 3) << 3;
            u64 aA[8], aB[8];
            #pragma unroll
            for (int j = 0; j < 8; ++j) { aA[j] = 0ull; aB[j] = 0ull; }

            const float4* r1 = (const float4*)&sT1[rl * STP];
            const float4* r2 = (const float4*)&sT2[rl * STP];
            const int qb = cx >> 2;
            #pragma unroll
            for (int qi = 0; qi < 6; ++qi) {
                const float4 A4 = r1[qb + qi];
                const float4 B4 = r2[qb + qi];
                u64 pa, pb; float a0,a1,b0,b1,a2,a3,b2,b3;
                pa = add2(pk2(A4.x, A4.y), NEGH); up2(pa, a0, a1);
                pb = add2(pk2(B4.x, B4.y), NEGH); up2(pb, b0, b1);
                { const int k = 4 * qi - 3;
                  if (k >= 0 && k <= 17) ACCS(k, a0, b0);
                  if (k + 1 >= 0 && k + 1 <= 17) ACCS(k + 1, a1, b1); }
                pa = add2(pk2(A4.z, A4.w), NEGH); up2(pa, a2, a3);
                pb = add2(pk2(B4.z, B4.w), NEGH); up2(pb, b2, b3);
                { const int k = 4 * qi - 1;
                  if (k >= 0 && k <= 17) ACCS(k, a2, b2);
                  if (k + 1 <= 17) ACCS(k + 1, a3, b3); }
            }

            #pragma unroll
            for (int j = 0; j < 8; ++j) {
                float m1, m2, s, xy;
                up2(aA[j], m1, m2);
                up2(aB[j], s, xy);
                H2x2 h;
                h.a = __floats2half2_rn(m1, m2);
                h.b = __floats2half2_rn(s, xy);
                sH[r * HP + cx + j] = h;
            }
        }
        __syncthreads();                         // all reads of buffer done
        if (ch == 0 && tid == 0) {
            asm volatile("fence.proxy.async.shared::cta;" ::: "memory");
            TMA_CHUNK(y0 + 32);                  // chunk 1: staged rows 37..73
        }
    }

    // ---- V-pass + SSIM: 8 warps x 8 rows = 64 rows exact ----
    __half2 wh[6];
    #pragma unroll
    for (int i = 0; i < 6; ++i) wh[i] = __float2half2_rn(sW[i]);
    const int x  = tid & 31;
    const int ys = (tid >> 5) << 3;
    __half2 vA[8], vB[8];
    const __half2 hz = __float2half2_rn(0.f);
    #pragma unroll
    for (int j = 0; j < 8; ++j) { vA[j] = hz; vB[j] = hz; }
    #pragma unroll
    for (int k = 0; k < 18; ++k) {
        const H2x2 h = sH[(ys + k) * HP + x];
        #pragma unroll
        for (int j = 0; j < 8; ++j) {
            const int t = k - j;
            if (t >= 0 && t <= 10) {
                const int wi = (t < 6) ? t : 10 - t;
                vA[j] = __hfma2(wh[wi], h.a, vA[j]);
                vB[j] = __hfma2(wh[wi], h.b, vB[j]);
            }
        }
    }
    float local = 0.f;
    #pragma unroll
    for (int j = 0; j < 8; ++j) {
        const float2 m  = __half22float2(vA[j]);
        const float2 sx = __half22float2(vB[j]);
        const float t2 = m.x + m.y;
        const float p  = m.x * m.y;
        const float q2 = fmaf(m.x, m.x, m.y * m.y);
        const float mu12 = fmaf(0.5f, t2, p + 0.25f);
        const float A2   = q2 + t2 + 0.5f;
        const float num = fmaf(2.f, mu12, C1F) * fmaf(2.f, sx.y - p, C2F);
        const float den = (A2 + C1F) * ((sx.x - q2) + C2F);
        local += (1.f - __fdividef(num, den)) * 0.5f;
    }
    #pragma unroll
    for (int o = 16; o; o >>= 1) local += __shfl_xor_sync(0xffffffffu, local, o);
    if ((tid & 31) == 0) sWarp[tid >> 5] = local;
    __syncthreads();
    if (tid == 0) {
        float bs = 0.f;
        #pragma unroll
        for (int i = 0; i < 8; ++i) bs += sWarp[i];
        g_part[((int)blockIdx.z * GY + (int)blockIdx.y) * GX + (int)blockIdx.x] = bs;
    }
}

// Naive fallback (only if tensormap encode fails)
__global__ __launch_bounds__(256) void dssim_naive(
    const float* __restrict__ im1, const float* __restrict__ im2, const float* __restrict__ kern)
{
    __shared__ float sK[121], sWarp[8];
    const int tid = threadIdx.x;
    if (tid < 121) sK[tid] = kern[tid];
    __syncthreads();
    const int x = blockIdx.x * TW + (tid & 31);
    const int yb = blockIdx.y * TH + (tid >> 5) * 8;
    const size_t pb = (size_t)blockIdx.z * IMH * IMW;
    float local = 0.f;
    for (int py = 0; py < 8; ++py) {
        const int y = yb + py;
        float m1 = 0, m2 = 0, xx = 0, yy = 0, xy = 0;
        for (int t = 0; t < 121; ++t) {
            const int gy = y + t / 11 - 5, gx = x + t % 11 - 5;
            float a = 0, b = 0;
            if ((unsigned)gy < IMH && (unsigned)gx < IMW) {
                a = im1[pb + (size_t)gy * IMW + gx]; b = im2[pb + (size_t)gy * IMW + gx];
            }
            const float w = sK[t];
            m1 += w * a; m2 += w * b; xx += w * a * a; yy += w * b * b; xy += w * a * b;
        }
        const float mu12 = m1 * m2, A2 = m1 * m1 + m2 * m2;
        const float num = (2.f * mu12 + C1F) * (2.f * (xy - mu12) + C2F);
        const float den = (A2 + C1F) * ((xx + yy - A2) + C2F);
        local += (1.f - num / den) * 0.5f;
    }
    #pragma unroll
    for (int o = 16; o; o >>= 1) local += __shfl_xor_sync(0xffffffffu, local, o);
    if ((tid & 31) == 0) sWarp[tid >> 5] = local;
    __syncthreads();
    if (tid == 0) {
        float bs = 0.f;
        #pragma unroll
        for (int i = 0; i < 8; ++i) bs += sWarp[i];
        g_part[((int)blockIdx.z * GY + (int)blockIdx.y) * GX + (int)blockIdx.x] = bs;
    }
}

__global__ __launch_bounds__(256) void dssim_reduce1()
{
    __shared__ double sd[256];
    const int t = threadIdx.x;
    sd[t] = (double)g_part[blockIdx.x * 256 + t];
    __syncthreads();
    #pragma unroll
    for (int o = 128; o; o >>= 1) { if (t < o) sd[t] += sd[t + o]; __syncthreads(); }
    if (t == 0) g_part2[blockIdx.x] = sd[0];
}

__global__ __launch_bounds__(64) void dssim_reduce2(float* __restrict__ out)
{
    __shared__ double sd[64];
    const int t = threadIdx.x;
    sd[t] = (t < NRED1) ? g_part2[t] : 0.0;
    __syncthreads();
    #pragma unroll
    for (int o = 32; o; o >>= 1) { if (t < o) sd[t] += sd[t + o]; __syncthreads(); }
    if (t == 0) out[0] = (float)(sd[0] / (double)(32.0 * 3.0 * 512.0 * 512.0));
}

typedef CUresult (*PFN_enc)(CUtensorMap*, CUtensorMapDataType, cuuint32_t, void*,
    const cuuint64_t*, const cuuint64_t*, const cuuint32_t*, const cuuint32_t*,
    CUtensorMapInterleave, CUtensorMapSwizzle, CUtensorMapL2promotion, CUtensorMapFloatOOBfill);

static bool build_tmap(PFN_enc enc, CUtensorMap* tm, const void* ptr)
{
    cuuint64_t dims[3] = {IMW, IMH, 96};
    cuuint64_t str[2] = {IMW * 4ull, (cuuint64_t)IMH * IMW * 4ull};
    cuuint32_t box[3] = {STP, CROWS, 1};
    cuuint32_t es[3] = {1, 1, 1};
    return enc(tm, CU_TENSOR_MAP_DATA_TYPE_FLOAT32, 3, (void*)ptr, dims, str, box, es,
               CU_TENSOR_MAP_INTERLEAVE_NONE, CU_TENSOR_MAP_SWIZZLE_NONE,
               CU_TENSOR_MAP_L2_PROMOTION_L2_128B, CU_TENSOR_MAP_FLOAT_OOB_FILL_NONE) == CUDA_SUCCESS;
}

extern "C" void kernel_launch(void* const* d_in, const int* in_sizes, int n_in,
                              void* d_out, int out_size)
{
    const float* im1 = (const float*)d_in[0];
    const float* im2 = (const float*)d_in[1];
    const float* kern = (const float*)d_in[2];
    float* out = (float*)d_out;
    dim3 grid(GX, GY, 96);   // 16 x 8 x 96 tiles of 32x64

    PFN_enc enc = nullptr;
    {
        void* fp = nullptr;
        cudaDriverEntryPointQueryResult st = cudaDriverEntryPointSymbolNotFound;
        if (cudaGetDriverEntryPoint("cuTensorMapEncodeTiled", &fp, cudaEnableDefault, &st) == cudaSuccess &&
            st == cudaDriverEntryPointSuccess)
            enc = (PFN_enc)fp;
    }
    CUtensorMap tm1, tm2;
    if (enc && build_tmap(enc, &tm1, im1) && build_tmap(enc, &tm2, im2))
        dssim_tma<<<grid, 256>>>(tm1, tm2, kern);
    else
        dssim_naive<<<grid, 256>>>(im1, im2, kern);

    dssim_reduce1<<<NRED1, 256>>>();
    dssim_reduce2<<<1, 64>>>(out);
}